// round 2
// baseline (speedup 1.0000x reference)
#include <cuda_runtime.h>
#include <cuda_bf16.h>

// y[m] = 0.75 * sum_k( x[m,k] * wcs[k] ),  wcs[k] = sum_n weight[n,k]
// M = K = N = 8192, fp32. HBM-streaming: 512 MiB compulsory traffic.
//
// Single persistent kernel, 128 blocks x 1024 threads (all co-resident):
//   Phase A: column-sum of weight -> g_wcs (atomicAdd, 64 adds/address)
//   grid barrier (spin on g_bar)
//   Phase B: warp-per-row-pair dot products (exactly 2 rows per warp)
//   Last-finishing block zeroes g_wcs and resets g_bar for the next replay.

#define MM 8192
#define KK 8192
#define NN 8192
#define GRID 128
#define THREADS 1024

__device__ float    g_wcs[KK];   // zero at module load; re-zeroed by last block
__device__ unsigned g_bar = 0;   // barrier/arrival counter; reset by last block

__device__ __forceinline__ float dot4(float4 a, float4 b, float acc) {
    acc = fmaf(a.x, b.x, acc);
    acc = fmaf(a.y, b.y, acc);
    acc = fmaf(a.z, b.z, acc);
    acc = fmaf(a.w, b.w, acc);
    return acc;
}

__global__ __launch_bounds__(THREADS, 1)
void fused_kernel(const float* __restrict__ x,
                  const float* __restrict__ weight,
                  float* __restrict__ out) {
    const int tid = threadIdx.x;
    const int gt  = blockIdx.x * THREADS + tid;   // 0 .. 131071

    // ---------------- Phase A: column-sum of weight ----------------
    {
        const int col4 = gt & 2047;        // float4 column index (0..2047)
        const int grp  = gt >> 11;         // row group (0..63), 128 rows each
        const float4* __restrict__ w4 =
            reinterpret_cast<const float4*>(weight) + (size_t)(grp * 128) * 2048 + col4;

        float4 acc = make_float4(0.f, 0.f, 0.f, 0.f);
#pragma unroll 8
        for (int r = 0; r < 128; ++r) {
            float4 v = w4[(size_t)r * 2048];
            acc.x += v.x; acc.y += v.y; acc.z += v.z; acc.w += v.w;
        }
        const int col = col4 * 4;
        atomicAdd(&g_wcs[col + 0], acc.x);
        atomicAdd(&g_wcs[col + 1], acc.y);
        atomicAdd(&g_wcs[col + 2], acc.z);
        atomicAdd(&g_wcs[col + 3], acc.w);
    }

    // ---------------- grid barrier ----------------
    __syncthreads();
    if (tid == 0) {
        __threadfence();
        atomicAdd(&g_bar, 1u);
        while (*(volatile unsigned*)&g_bar < GRID) { }
        __threadfence();
    }
    __syncthreads();

    // ---------------- Phase B: row dot products ----------------
    {
        const int gwid = gt >> 5;          // global warp id (0..4095)
        const int lane = tid & 31;
        const int r0 = gwid * 2;
        const int r1 = r0 + 1;

        const float4* __restrict__ x0 = reinterpret_cast<const float4*>(x) + (size_t)r0 * 2048;
        const float4* __restrict__ x1 = reinterpret_cast<const float4*>(x) + (size_t)r1 * 2048;
        const float4* __restrict__ w4 = reinterpret_cast<const float4*>(g_wcs);

        float acc0 = 0.f, acc1 = 0.f;
#pragma unroll 4
        for (int i = lane; i < 2048; i += 32) {
            float4 wv = w4[i];
            acc0 = dot4(x0[i], wv, acc0);
            acc1 = dot4(x1[i], wv, acc1);
        }

#pragma unroll
        for (int off = 16; off > 0; off >>= 1) {
            acc0 += __shfl_down_sync(0xFFFFFFFFu, acc0, off);
            acc1 += __shfl_down_sync(0xFFFFFFFFu, acc1, off);
        }
        if (lane == 0) {
            out[r0] = 0.75f * acc0;
            out[r1] = 0.75f * acc1;
        }
    }

    // ---------------- cleanup by last-finishing block ----------------
    __syncthreads();
    __shared__ bool s_last;
    if (tid == 0) {
        __threadfence();
        unsigned prev = atomicAdd(&g_bar, 1u);
        s_last = (prev == 2u * GRID - 1u);
    }
    __syncthreads();
    if (s_last) {
        for (int i = tid; i < KK; i += THREADS) g_wcs[i] = 0.0f;
        if (tid == 0) {
            __threadfence();
            g_bar = 0;
        }
    }
}

extern "C" void kernel_launch(void* const* d_in, const int* in_sizes, int n_in,
                              void* d_out, int out_size) {
    const float* x      = (const float*)d_in[0];
    const float* weight = (const float*)d_in[1];
    float* out = (float*)d_out;

    fused_kernel<<<GRID, THREADS>>>(x, weight, out);
}

// round 3
// speedup vs baseline: 1.0220x; 1.0220x over previous
#include <cuda_runtime.h>
#include <cuda_bf16.h>

// y[m] = 0.75 * sum_k( x[m,k] * wcs[k] ),  wcs[k] = sum_n weight[n,k]
// M = K = N = 8192, fp32. HBM-streaming: 512 MiB compulsory traffic.
//
// Single persistent kernel, 148 blocks x 1024 threads (exactly 1 CTA per SM):
//   Phase A: column-sum of weight -> g_wcs (atomicAdd, 74 adds/address)
//   grid barrier (spin on g_bar)
//   Phase B: warp-per-row dot products, rows striped across blocks
//   Last-finishing block zeroes g_wcs and resets g_bar for the next replay.

#define MM 8192
#define KK 8192
#define NN 8192
#define GRID 148
#define THREADS 1024
#define COL4 2048            // float4 columns per row
#define ROWGRP (GRID * THREADS / COL4)   // 74 row groups in phase A

__device__ float    g_wcs[KK];   // zero at module load; re-zeroed by last block
__device__ unsigned g_bar = 0;   // barrier/arrival counter; reset by last block

__device__ __forceinline__ float dot4(float4 a, float4 b, float acc) {
    acc = fmaf(a.x, b.x, acc);
    acc = fmaf(a.y, b.y, acc);
    acc = fmaf(a.z, b.z, acc);
    acc = fmaf(a.w, b.w, acc);
    return acc;
}

__global__ __launch_bounds__(THREADS, 1)
void fused_kernel(const float* __restrict__ x,
                  const float* __restrict__ weight,
                  float* __restrict__ out) {
    const int tid = threadIdx.x;
    const int gt  = blockIdx.x * THREADS + tid;   // 0 .. 151551

    // ---------------- Phase A: column-sum of weight ----------------
    {
        const int col4 = gt & (COL4 - 1);   // float4 column (0..2047)
        const int grp  = gt >> 11;          // row group (0..73)
        const float4* __restrict__ w4 =
            reinterpret_cast<const float4*>(weight) + col4;

        float4 acc = make_float4(0.f, 0.f, 0.f, 0.f);
        // rows r = grp, grp+74, ... (110 or 111 rows per thread)
        int r = grp;
#pragma unroll 4
        for (; r < NN; r += ROWGRP) {
            float4 v = __ldcs(w4 + (size_t)r * COL4);
            acc.x += v.x; acc.y += v.y; acc.z += v.z; acc.w += v.w;
        }
        const int col = col4 * 4;
        atomicAdd(&g_wcs[col + 0], acc.x);
        atomicAdd(&g_wcs[col + 1], acc.y);
        atomicAdd(&g_wcs[col + 2], acc.z);
        atomicAdd(&g_wcs[col + 3], acc.w);
    }

    // ---------------- grid barrier ----------------
    __syncthreads();
    if (tid == 0) {
        __threadfence();
        atomicAdd(&g_bar, 1u);
        while (*(volatile unsigned*)&g_bar < GRID) { }
        __threadfence();
    }
    __syncthreads();

    // ---------------- Phase B: row dot products ----------------
    {
        const int wid  = tid >> 5;     // warp in block (0..31)
        const int lane = tid & 31;
        const float4* __restrict__ wv4 = reinterpret_cast<const float4*>(g_wcs);

        // rows for this block: row = blockIdx.x + GRID*j, j = 0.. (55 or 56 rows)
        // warp wid takes j = wid, wid+32, ...
        for (int j = wid; ; j += 32) {
            const int row = blockIdx.x + GRID * j;
            if (row >= MM) break;

            const float4* __restrict__ xr =
                reinterpret_cast<const float4*>(x) + (size_t)row * COL4;

            float acc = 0.f;
#pragma unroll 8
            for (int i = lane; i < COL4; i += 32) {
                acc = dot4(__ldcs(xr + i), wv4[i], acc);
            }

#pragma unroll
            for (int off = 16; off > 0; off >>= 1)
                acc += __shfl_down_sync(0xFFFFFFFFu, acc, off);

            if (lane == 0) out[row] = 0.75f * acc;
        }
    }

    // ---------------- cleanup by last-finishing block ----------------
    __syncthreads();
    __shared__ bool s_last;
    if (tid == 0) {
        __threadfence();
        unsigned prev = atomicAdd(&g_bar, 1u);
        s_last = (prev == 2u * GRID - 1u);
    }
    __syncthreads();
    if (s_last) {
        for (int i = tid; i < KK; i += THREADS) g_wcs[i] = 0.0f;
        if (tid == 0) {
            __threadfence();
            g_bar = 0;
        }
    }
}

extern "C" void kernel_launch(void* const* d_in, const int* in_sizes, int n_in,
                              void* d_out, int out_size) {
    const float* x      = (const float*)d_in[0];
    const float* weight = (const float*)d_in[1];
    float* out = (float*)d_out;

    fused_kernel<<<GRID, THREADS>>>(x, weight, out);
}

// round 4
// speedup vs baseline: 1.0715x; 1.0484x over previous
#include <cuda_runtime.h>
#include <cuda_bf16.h>

// y[m] = 0.75 * sum_k( x[m,k] * wcs[k] ),  wcs[k] = sum_n weight[n,k]
// x: [M,K] fp32, weight: [N,K] fp32, out: [M,1] fp32.  M=K=N=8192.
// Pure HBM-streaming problem: 512 MiB compulsory traffic.
//
// Two kernels (proven fastest structure):
//  1) colsum: 512 blocks x 256 thr, each thread sums 128 rows of one float4
//     column group, 4 atomicAdds into g_wcs (64-way fan-in per address).
//  2) rowdot: 8192 blocks x 256 thr, one block per output row.
//     The LAST-finishing rowdot block re-zeroes g_wcs and resets the counter
//     so the next graph replay starts clean (g_wcs is zero at module load).

#define MM 8192
#define KK 8192
#define NN 8192

__device__ float    g_wcs[KK];    // zero-initialized at module load
__device__ unsigned g_done = 0;   // rowdot completion counter

// ------------------------------------------------- column sum of weight[N,K]
#define CS_THREADS 256
#define ROW_CHUNKS 64
#define ROWS_PER_CHUNK (NN / ROW_CHUNKS)  // 128

__global__ __launch_bounds__(CS_THREADS) void colsum_kernel(const float* __restrict__ weight) {
    const int col4 = blockIdx.x * CS_THREADS + threadIdx.x;   // float4 index into a row
    const int row0 = blockIdx.y * ROWS_PER_CHUNK;

    const float4* __restrict__ w4 = reinterpret_cast<const float4*>(weight);
    const int row_stride4 = KK / 4;  // 2048

    float4 acc = make_float4(0.f, 0.f, 0.f, 0.f);
    const float4* p = w4 + (size_t)row0 * row_stride4 + col4;

#pragma unroll 8
    for (int r = 0; r < ROWS_PER_CHUNK; ++r) {
        float4 v = p[(size_t)r * row_stride4];
        acc.x += v.x; acc.y += v.y; acc.z += v.z; acc.w += v.w;
    }

    const int col = col4 * 4;
    atomicAdd(&g_wcs[col + 0], acc.x);
    atomicAdd(&g_wcs[col + 1], acc.y);
    atomicAdd(&g_wcs[col + 2], acc.z);
    atomicAdd(&g_wcs[col + 3], acc.w);
}

// ------------------------------------------------- per-row dot with g_wcs
#define DOT_THREADS 256

__global__ __launch_bounds__(DOT_THREADS) void rowdot_kernel(const float* __restrict__ x,
                                                             float* __restrict__ out) {
    const int row = blockIdx.x;
    const float4* __restrict__ x4 = reinterpret_cast<const float4*>(x) + (size_t)row * (KK / 4);
    const float4* __restrict__ w4 = reinterpret_cast<const float4*>(g_wcs);

    float acc = 0.0f;
#pragma unroll
    for (int i = 0; i < (KK / 4) / DOT_THREADS; ++i) {   // 8 iterations
        const int idx = i * DOT_THREADS + threadIdx.x;
        float4 xv = x4[idx];
        float4 wv = w4[idx];
        acc = fmaf(xv.x, wv.x, acc);
        acc = fmaf(xv.y, wv.y, acc);
        acc = fmaf(xv.z, wv.z, acc);
        acc = fmaf(xv.w, wv.w, acc);
    }

    // warp reduce
#pragma unroll
    for (int off = 16; off > 0; off >>= 1)
        acc += __shfl_down_sync(0xFFFFFFFFu, acc, off);

    __shared__ float warp_sums[DOT_THREADS / 32];
    const int lane = threadIdx.x & 31;
    const int wid  = threadIdx.x >> 5;
    if (lane == 0) warp_sums[wid] = acc;
    __syncthreads();

    if (wid == 0) {
        float s = (lane < DOT_THREADS / 32) ? warp_sums[lane] : 0.0f;
#pragma unroll
        for (int off = 4; off > 0; off >>= 1)
            s += __shfl_down_sync(0xFFFFFFFFu, s, off);
        if (lane == 0) out[row] = 0.75f * s;
    }
}

// Cleanup: last-finishing block zeroes g_wcs for the next replay.
__global__ __launch_bounds__(DOT_THREADS) void rowdot_cleanup_probe() {}

__device__ __forceinline__ void rowdot_tail_cleanup() {}

// (cleanup is folded into rowdot via a second kernel body below)
__global__ __launch_bounds__(DOT_THREADS) void rowdot_kernel_tail(const float* __restrict__ x,
                                                                  float* __restrict__ out) {
    rowdot_kernel; // unused
}

extern "C" void kernel_launch(void* const* d_in, const int* in_sizes, int n_in,
                              void* d_out, int out_size);

// Real rowdot with cleanup integrated:
__global__ __launch_bounds__(DOT_THREADS) void rowdot_clean_kernel(const float* __restrict__ x,
                                                                   float* __restrict__ out) {
    const int row = blockIdx.x;
    const float4* __restrict__ x4 = reinterpret_cast<const float4*>(x) + (size_t)row * (KK / 4);
    const float4* __restrict__ w4 = reinterpret_cast<const float4*>(g_wcs);

    float acc = 0.0f;
#pragma unroll
    for (int i = 0; i < (KK / 4) / DOT_THREADS; ++i) {
        const int idx = i * DOT_THREADS + threadIdx.x;
        float4 xv = x4[idx];
        float4 wv = w4[idx];
        acc = fmaf(xv.x, wv.x, acc);
        acc = fmaf(xv.y, wv.y, acc);
        acc = fmaf(xv.z, wv.z, acc);
        acc = fmaf(xv.w, wv.w, acc);
    }

#pragma unroll
    for (int off = 16; off > 0; off >>= 1)
        acc += __shfl_down_sync(0xFFFFFFFFu, acc, off);

    __shared__ float warp_sums[DOT_THREADS / 32];
    const int lane = threadIdx.x & 31;
    const int wid  = threadIdx.x >> 5;
    if (lane == 0) warp_sums[wid] = acc;
    __syncthreads();

    if (wid == 0) {
        float s = (lane < DOT_THREADS / 32) ? warp_sums[lane] : 0.0f;
#pragma unroll
        for (int off = 4; off > 0; off >>= 1)
            s += __shfl_down_sync(0xFFFFFFFFu, s, off);
        if (lane == 0) out[row] = 0.75f * s;
    }

    // ---- last-finishing block zeroes g_wcs for the next graph replay ----
    __syncthreads();
    __shared__ bool s_last;
    if (threadIdx.x == 0) {
        __threadfence();
        unsigned prev = atomicAdd(&g_done, 1u);
        s_last = (prev == (unsigned)(MM - 1));
    }
    __syncthreads();
    if (s_last) {
        for (int i = threadIdx.x; i < KK; i += DOT_THREADS) g_wcs[i] = 0.0f;
        if (threadIdx.x == 0) {
            __threadfence();
            g_done = 0;
        }
    }
}

// ---------------------------------------------------------------- launcher
extern "C" void kernel_launch(void* const* d_in, const int* in_sizes, int n_in,
                              void* d_out, int out_size) {
    const float* x      = (const float*)d_in[0];
    const float* weight = (const float*)d_in[1];
    float* out = (float*)d_out;

    dim3 cs_grid(KK / (CS_THREADS * 4), ROW_CHUNKS);  // (8, 64)
    colsum_kernel<<<cs_grid, CS_THREADS>>>(weight);

    rowdot_clean_kernel<<<MM, DOT_THREADS>>>(x, out);
}